// round 15
// baseline (speedup 1.0000x reference)
#include <cuda_runtime.h>
#include <cuda_bf16.h>
#include <mma.h>
#include <cstdint>

using namespace nvcuda;

#define NN 100000
#define EE 640000
#define HH 128
#define GG 64
#define CC 7

#define SCHUNK 256
#define SBLOCKS ((NN + SCHUNK - 1) / SCHUNK)   // 391
#define TROWS 64
#define GT2 ((NN + TROWS - 1) / TROWS)         // 1563 gemm tiles
#define APAD 136                               // bf16 smem row stride (+16B pad)
#define PCH 16                                 // pool chunks per graph

// ---------------- device scratch (no allocation allowed) ----------------
__device__ int   g_deg[NN];
__device__ float g_dinv[NN];
__device__ int   g_rowptr[NN + 1];
__device__ int   g_cursor[NN];
__device__ int   g_src[EE];
__device__ float g_w[EE];
__device__ float g_hA[(size_t)NN * HH];
__device__ float g_hB[(size_t)NN * HH];
__device__ float g_pool[GG * HH];
__device__ int   g_cnt[GG];
__device__ int   g_blksum[SBLOCKS];
__device__ int   g_blkoff[SBLOCKS];
// pre-split weight: [matrix 0=W2,1=W3][hi/lo][k*HH+n] (native row-major K x N)
__device__ __nv_bfloat16 g_Wsp[2][2][HH * HH];

// ---------------- helpers ----------------
__device__ __forceinline__ float4 f4_fma(float a, float4 v, float4 acc) {
    acc.x += a * v.x; acc.y += a * v.y; acc.z += a * v.z; acc.w += a * v.w;
    return acc;
}

// ---------------- init ----------------
__global__ void init_kernel() {
    int i = blockIdx.x * blockDim.x + threadIdx.x;
    if (i < NN) g_deg[i] = 1;
    if (i < GG) g_cnt[i] = 0;
    if (i < GG * HH) g_pool[i] = 0.f;
}

__global__ void deg_kernel(const int* __restrict__ col) {
    int e = blockIdx.x * blockDim.x + threadIdx.x;
    if (e < EE) atomicAdd(&g_deg[col[e]], 1);
}

__global__ void dinv_kernel(const int* __restrict__ batch) {
    int i = blockIdx.x * blockDim.x + threadIdx.x;
    if (i < NN) {
        g_dinv[i] = rsqrtf((float)g_deg[i]);
        atomicAdd(&g_cnt[batch[i]], 1);
    }
}

// ---------------- weight split prep: W[k,n] -> hi/lo bf16 (same layout) ----------------
__global__ void prepw_kernel(const float* __restrict__ W2, const float* __restrict__ W3) {
    int idx = blockIdx.x * blockDim.x + threadIdx.x;       // 2*16384
    if (idx >= 2 * HH * HH) return;
    int m = idx >> 14;
    int e = idx & (HH * HH - 1);
    float w = (m ? W3 : W2)[e];
    __nv_bfloat16 wh = __float2bfloat16_rn(w);
    float wl = w - __bfloat162float(wh);
    g_Wsp[m][0][e] = wh;
    g_Wsp[m][1][e] = __float2bfloat16_rn(wl);
}

// ---------------- multi-block scan ----------------
__global__ void scanA_kernel() {
    int i = blockIdx.x * SCHUNK + threadIdx.x;
    int v = (i < NN) ? (g_deg[i] - 1) : 0;
    #pragma unroll
    for (int off = 16; off > 0; off >>= 1) v += __shfl_xor_sync(0xffffffffu, v, off);
    __shared__ int ws[8];
    int lane = threadIdx.x & 31, wid = threadIdx.x >> 5;
    if (lane == 0) ws[wid] = v;
    __syncthreads();
    if (threadIdx.x == 0) {
        int s = 0;
        #pragma unroll
        for (int j = 0; j < 8; ++j) s += ws[j];
        g_blksum[blockIdx.x] = s;
    }
}

__global__ void scanB_kernel() {
    __shared__ int sm[512];
    int t = threadIdx.x;
    int v = (t < SBLOCKS) ? g_blksum[t] : 0;
    sm[t] = v;
    __syncthreads();
    #pragma unroll
    for (int off = 1; off < 512; off <<= 1) {
        int u = (t >= off) ? sm[t - off] : 0;
        __syncthreads();
        sm[t] += u;
        __syncthreads();
    }
    if (t < SBLOCKS) g_blkoff[t] = sm[t] - v;
    if (t == SBLOCKS - 1) g_rowptr[NN] = sm[t];
}

__global__ void scanC_kernel() {
    int i = blockIdx.x * SCHUNK + threadIdx.x;
    int v = (i < NN) ? (g_deg[i] - 1) : 0;
    int lane = threadIdx.x & 31, wid = threadIdx.x >> 5;
    int inc = v;
    #pragma unroll
    for (int off = 1; off <= 16; off <<= 1) {
        int n = __shfl_up_sync(0xffffffffu, inc, off);
        if (lane >= off) inc += n;
    }
    __shared__ int ws[8];
    if (lane == 31) ws[wid] = inc;
    __syncthreads();
    if (threadIdx.x == 0) {
        int run = 0;
        #pragma unroll
        for (int j = 0; j < 8; ++j) { int t = ws[j]; ws[j] = run; run += t; }
    }
    __syncthreads();
    int ex = inc - v + ws[wid] + g_blkoff[blockIdx.x];
    if (i < NN) { g_rowptr[i] = ex; g_cursor[i] = ex; }
}

// ---------------- CSR fill ----------------
__global__ void fill_kernel(const int* __restrict__ rowi, const int* __restrict__ coli) {
    int e = blockIdx.x * blockDim.x + threadIdx.x;
    if (e >= EE) return;
    int r = rowi[e], c = coli[e];
    int p = atomicAdd(&g_cursor[c], 1);
    g_src[p] = r;
    g_w[p]   = g_dinv[r] * g_dinv[c];
}

// ---------------- layer 1 (F_IN=1 scalar aggregation + outer product) ----------------
__global__ void layer1_kernel(const float* __restrict__ x,
                              const float* __restrict__ W1,
                              const float* __restrict__ b1) {
    int warp = (blockIdx.x * blockDim.x + threadIdx.x) >> 5;
    int lane = threadIdx.x & 31;
    if (warp >= NN) return;
    const int i = warp;
    int ps = g_rowptr[i], pe = g_rowptr[i + 1];
    float s = 0.f;
    for (int p = ps + lane; p < pe; p += 32)
        s += g_w[p] * __ldg(x + g_src[p]);
    #pragma unroll
    for (int off = 16; off > 0; off >>= 1) s += __shfl_xor_sync(0xffffffffu, s, off);
    float di = g_dinv[i];
    s += di * di * __ldg(x + i);
    float4 wv = ((const float4*)W1)[lane];
    float4 bv = ((const float4*)b1)[lane];
    float4 o;
    o.x = fmaxf(s * wv.x + bv.x, 0.f);
    o.y = fmaxf(s * wv.y + bv.y, 0.f);
    o.z = fmaxf(s * wv.z + bv.z, 0.f);
    o.w = fmaxf(s * wv.w + bv.w, 0.f);
    *(float4*)(g_hA + (size_t)i * HH + lane * 4) = o;
}

// ---------------- wmma bf16 GEMM: C[N,128] = A[N,128] @ W[128,128] --------------------
// 3-pass error-compensated split: Ah*Wh + Al*Wh + Ah*Wl, fp32 accumulators.
// 64-row tiles, two B buffers, smem = 104.4 KB -> 2 CTAs/SM (measured optimum, R8).
#define SM_A (TROWS * APAD)                    // one A tile (bf16 elems)
#define SM_B (HH * APAD)                       // one B tile
#define GEMM_SMEM ((2 * SM_A + 2 * SM_B) * 2)  // 104448 B

__global__ __launch_bounds__(256, 2) void gemm_wmma_kernel(const float* __restrict__ A,
                                                           int wsel,
                                                           float* __restrict__ Cout) {
    extern __shared__ __align__(16) char smx[];
    __nv_bfloat16* Ah = (__nv_bfloat16*)smx;
    __nv_bfloat16* Al = Ah + SM_A;
    __nv_bfloat16* Bh = Al + SM_A;
    __nv_bfloat16* Bl = Bh + SM_B;
    const int tid = threadIdx.x;
    const int row0 = blockIdx.x * TROWS;

    // copy pre-split W (row-major [k][n]) into padded smem
    {
        const uint4* wh4 = (const uint4*)g_Wsp[wsel][0];
        const uint4* wl4 = (const uint4*)g_Wsp[wsel][1];
        #pragma unroll
        for (int i = tid; i < 2048; i += 256) {      // 128 rows x 16 uint4
            int r = i >> 4, c8 = (i & 15) * 8;
            *(uint4*)(Bh + r * APAD + c8) = wh4[i];
            *(uint4*)(Bl + r * APAD + c8) = wl4[i];
        }
    }
    // convert A tile (64x128 fp32 -> bf16 hi/lo, padded rows)
    #pragma unroll
    for (int it = 0; it < 8; ++it) {
        int idx = tid + it * 256;                    // 2048 float4s
        int r = idx >> 5;
        int c = (idx & 31) * 4;
        float4 v = make_float4(0.f, 0.f, 0.f, 0.f);
        if (row0 + r < NN) v = *(const float4*)(A + (size_t)(row0 + r) * HH + c);
        __nv_bfloat162 h01 = __floats2bfloat162_rn(v.x, v.y);
        __nv_bfloat162 h23 = __floats2bfloat162_rn(v.z, v.w);
        __nv_bfloat162 l01 = __floats2bfloat162_rn(v.x - __bfloat162float(h01.x),
                                                   v.y - __bfloat162float(h01.y));
        __nv_bfloat162 l23 = __floats2bfloat162_rn(v.z - __bfloat162float(h23.x),
                                                   v.w - __bfloat162float(h23.y));
        uint2 ph, pl;
        ph.x = *reinterpret_cast<uint32_t*>(&h01);
        ph.y = *reinterpret_cast<uint32_t*>(&h23);
        pl.x = *reinterpret_cast<uint32_t*>(&l01);
        pl.y = *reinterpret_cast<uint32_t*>(&l23);
        *(uint2*)(Ah + r * APAD + c) = ph;
        *(uint2*)(Al + r * APAD + c) = pl;
    }
    __syncthreads();

    // warp tiling: 8 warps, each 16 rows x 64 cols
    const int w = tid >> 5;
    const int wr = (w >> 1) * 16;      // warp row offset (0..48)
    const int wc = (w & 1) * 64;       // warp col offset (0/64)

    wmma::fragment<wmma::accumulator, 16, 16, 16, float> c[4];
    #pragma unroll
    for (int j = 0; j < 4; ++j) wmma::fill_fragment(c[j], 0.f);

    #pragma unroll 1
    for (int pass = 0; pass < 3; ++pass) {
        const __nv_bfloat16* At = (pass == 1) ? Al : Ah;
        const __nv_bfloat16* Bt = (pass == 2) ? Bl : Bh;
        #pragma unroll 1
        for (int kt = 0; kt < 8; ++kt) {
            wmma::fragment<wmma::matrix_a, 16, 16, 16, __nv_bfloat16, wmma::row_major> a;
            wmma::fragment<wmma::matrix_b, 16, 16, 16, __nv_bfloat16, wmma::row_major> b[4];
            wmma::load_matrix_sync(a, At + wr * APAD + kt * 16, APAD);
            #pragma unroll
            for (int j = 0; j < 4; ++j)
                wmma::load_matrix_sync(b[j], Bt + (kt * 16) * APAD + wc + j * 16, APAD);
            #pragma unroll
            for (int j = 0; j < 4; ++j)
                wmma::mma_sync(c[j], a, b[j], c[j]);
        }
    }

    if (row0 + TROWS <= NN) {
        #pragma unroll
        for (int j = 0; j < 4; ++j)
            wmma::store_matrix_sync(Cout + (size_t)(row0 + wr) * HH + wc + j * 16,
                                    c[j], HH, wmma::mem_row_major);
    } else {
        // boundary tile: stage via smem (reuse Ah/Al region as float[64][128])
        float* stage = (float*)smx;
        __syncthreads();
        #pragma unroll
        for (int j = 0; j < 4; ++j)
            wmma::store_matrix_sync(stage + wr * HH + wc + j * 16, c[j], HH, wmma::mem_row_major);
        __syncthreads();
        const int valid = NN - row0;
        for (int idx = tid; idx < valid * 32; idx += 256) {
            int r = idx >> 5, cc = (idx & 31) * 4;
            *(float4*)(Cout + (size_t)(row0 + r) * HH + cc) = *(float4*)(stage + r * HH + cc);
        }
    }
}

// ---------------- propagation: lane-parallel index staging + shfl broadcast -----------
// One coalesced LDG fetches up to 32 (src,w) pairs; gather loop reads indices from
// registers via shuffle — removes the serial index-load -> gather dependency chain.
// NO launch_bounds (learned R12/R13). One-shot grid (persistent was neutral, R14).
template <bool RELU>
__global__ void prop_kernel(const float* __restrict__ hin,
                            float* __restrict__ hout,
                            const float* __restrict__ bias) {
    int warp = (blockIdx.x * blockDim.x + threadIdx.x) >> 5;
    int lane = threadIdx.x & 31;
    if (warp >= NN) return;
    const int i = warp;
    const float di = g_dinv[i];
    float4 self = *(const float4*)(hin + (size_t)i * HH + lane * 4);
    const float w0 = di * di;
    float4 acc;
    acc.x = w0 * self.x; acc.y = w0 * self.y; acc.z = w0 * self.z; acc.w = w0 * self.w;

    const int ps = g_rowptr[i];
    const int pe = g_rowptr[i + 1];
    for (int base = ps; base < pe; base += 32) {
        const int n = min(pe - base, 32);
        const int p = base + lane;
        int   sidx = 0;
        float sw   = 0.f;
        if (p < pe) { sidx = g_src[p]; sw = g_w[p]; }   // one coalesced load per chunk
        int k = 0;
        for (; k + 3 < n; k += 4) {
            int s0 = __shfl_sync(0xffffffffu, sidx, k);
            int s1 = __shfl_sync(0xffffffffu, sidx, k + 1);
            int s2 = __shfl_sync(0xffffffffu, sidx, k + 2);
            int s3 = __shfl_sync(0xffffffffu, sidx, k + 3);
            float wa = __shfl_sync(0xffffffffu, sw, k);
            float wb = __shfl_sync(0xffffffffu, sw, k + 1);
            float wc = __shfl_sync(0xffffffffu, sw, k + 2);
            float wd = __shfl_sync(0xffffffffu, sw, k + 3);
            float4 v0 = *(const float4*)(hin + (size_t)s0 * HH + lane * 4);
            float4 v1 = *(const float4*)(hin + (size_t)s1 * HH + lane * 4);
            float4 v2 = *(const float4*)(hin + (size_t)s2 * HH + lane * 4);
            float4 v3 = *(const float4*)(hin + (size_t)s3 * HH + lane * 4);
            acc = f4_fma(wa, v0, acc);
            acc = f4_fma(wb, v1, acc);
            acc = f4_fma(wc, v2, acc);
            acc = f4_fma(wd, v3, acc);
        }
        for (; k < n; ++k) {
            int   s0 = __shfl_sync(0xffffffffu, sidx, k);
            float wa = __shfl_sync(0xffffffffu, sw, k);
            float4 v0 = *(const float4*)(hin + (size_t)s0 * HH + lane * 4);
            acc = f4_fma(wa, v0, acc);
        }
    }

    float4 b = ((const float4*)bias)[lane];
    acc.x += b.x; acc.y += b.y; acc.z += b.z; acc.w += b.w;
    if (RELU) {
        acc.x = fmaxf(acc.x, 0.f); acc.y = fmaxf(acc.y, 0.f);
        acc.z = fmaxf(acc.z, 0.f); acc.w = fmaxf(acc.w, 0.f);
    }
    *(float4*)(hout + (size_t)i * HH + lane * 4) = acc;
}

// ---------------- mean pool: 16 chunks/graph, block-local sums + atomic merge ----------
__global__ void pool_kernel() {
    const int b = blockIdx.x;                 // GG*PCH blocks, 128 threads
    const int g = b / PCH, ch = b % PCH;
    int start = 0;
    #pragma unroll
    for (int j = 0; j < GG; ++j) if (j < g) start += g_cnt[j];
    const int cntg = g_cnt[g];
    const int per = (cntg + PCH - 1) / PCH;
    const int lo = start + ch * per;
    int hi = lo + per;
    const int end = start + cntg;
    if (hi > end) hi = end;
    const int col = threadIdx.x;              // 128
    float s = 0.f;
    for (int r = lo; r < hi; ++r)
        s += g_hA[(size_t)r * HH + col];
    if (hi > lo) atomicAdd(&g_pool[g * HH + col], s);
}

// ---------------- final linear (includes mean division) ----------------
__global__ void final_kernel(const float* __restrict__ Wl,
                             const float* __restrict__ bl,
                             float* __restrict__ out) {
    int t = threadIdx.x;
    if (t >= GG * CC) return;
    int g = t / CC, c = t % CC;
    float dot = 0.f;
    const float* pr = g_pool + g * HH;
    #pragma unroll 8
    for (int h = 0; h < HH; ++h)
        dot += pr[h] * __ldg(Wl + h * CC + c);
    float cnt = fmaxf((float)g_cnt[g], 1.f);
    out[t] = dot / cnt + __ldg(bl + c);
}

// ---------------- launch ----------------
extern "C" void kernel_launch(void* const* d_in, const int* in_sizes, int n_in,
                              void* d_out, int out_size) {
    const float* x    = (const float*)d_in[0];
    const int*   ei   = (const int*)d_in[1];
    const int*   batch= (const int*)d_in[2];
    const float* W1   = (const float*)d_in[3];
    const float* b1   = (const float*)d_in[4];
    const float* W2   = (const float*)d_in[5];
    const float* b2   = (const float*)d_in[6];
    const float* W3   = (const float*)d_in[7];
    const float* b3   = (const float*)d_in[8];
    const float* Wl   = (const float*)d_in[9];
    const float* bl   = (const float*)d_in[10];
    float* out = (float*)d_out;

    const int* erow = ei;
    const int* ecol = ei + EE;

    float *hA, *hB;
    cudaGetSymbolAddress((void**)&hA, g_hA);
    cudaGetSymbolAddress((void**)&hB, g_hB);

    cudaFuncSetAttribute(gemm_wmma_kernel, cudaFuncAttributeMaxDynamicSharedMemorySize, GEMM_SMEM);

    const int nblkN = (NN + 255) / 256;
    const int nblkE = (EE + 255) / 256;
    const int nwarpblk = (NN + 7) / 8;

    init_kernel<<<nblkN, 256>>>();
    deg_kernel<<<nblkE, 256>>>(ecol);
    dinv_kernel<<<nblkN, 256>>>(batch);
    prepw_kernel<<<(2 * HH * HH + 255) / 256, 256>>>(W2, W3);
    scanA_kernel<<<SBLOCKS, SCHUNK>>>();
    scanB_kernel<<<1, 512>>>();
    scanC_kernel<<<SBLOCKS, SCHUNK>>>();
    fill_kernel<<<nblkE, 256>>>(erow, ecol);

    layer1_kernel<<<nwarpblk, 256>>>(x, W1, b1);                     // -> hA (h1)
    gemm_wmma_kernel<<<GT2, 256, GEMM_SMEM>>>(hA, 0, hB);            // h1 @ W2 -> hB
    prop_kernel<true><<<nwarpblk, 256>>>(hB, hA, b2);                // -> hA (h2)
    gemm_wmma_kernel<<<GT2, 256, GEMM_SMEM>>>(hA, 1, hB);            // h2 @ W3 -> hB
    prop_kernel<false><<<nwarpblk, 256>>>(hB, hA, b3);               // -> hA (h3)
    pool_kernel<<<GG * PCH, 128>>>();
    final_kernel<<<1, 512>>>(Wl, bl, out);
}

// round 17
// speedup vs baseline: 1.2852x; 1.2852x over previous
#include <cuda_runtime.h>
#include <cuda_bf16.h>
#include <mma.h>
#include <cstdint>

using namespace nvcuda;

#define NN 100000
#define EE 640000
#define HH 128
#define GG 64
#define CC 7

#define SCHUNK 256
#define SBLOCKS ((NN + SCHUNK - 1) / SCHUNK)   // 391
#define TROWS 64
#define GT2 ((NN + TROWS - 1) / TROWS)         // 1563 gemm tiles
#define APAD 136                               // bf16 smem row stride (+16B pad)
#define PCH 16                                 // pool chunks per graph

// ---------------- device scratch (no allocation allowed) ----------------
__device__ int   g_deg[NN];
__device__ float g_dinv[NN];
__device__ int   g_rowptr[NN + 1];
__device__ int   g_cursor[NN];
__device__ int   g_src[EE];
__device__ float g_w[EE];
__device__ float g_hA[(size_t)NN * HH];
__device__ float g_hB[(size_t)NN * HH];
__device__ float g_pool[GG * HH];
__device__ int   g_cnt[GG];
__device__ int   g_blksum[SBLOCKS];
__device__ int   g_blkoff[SBLOCKS];
__device__ float g_zbias[HH];                  // zero bias for pure aggregation
__device__ float g_WF[HH * CC];                // W3 @ Wl (fused output weight)
__device__ float g_bf[CC];                     // b3 @ Wl + bl
// pre-split weight: [hi/lo][k*HH+n] for W2 only (W3 GEMM eliminated by associativity)
__device__ __nv_bfloat16 g_Wsp[2][HH * HH];

// ---------------- helpers ----------------
__device__ __forceinline__ float4 f4_fma(float a, float4 v, float4 acc) {
    acc.x += a * v.x; acc.y += a * v.y; acc.z += a * v.z; acc.w += a * v.w;
    return acc;
}

// ---------------- init ----------------
__global__ void init_kernel() {
    int i = blockIdx.x * blockDim.x + threadIdx.x;
    if (i < NN) g_deg[i] = 1;
    if (i < GG) g_cnt[i] = 0;
    if (i < GG * HH) g_pool[i] = 0.f;
    if (i < HH) g_zbias[i] = 0.f;
}

__global__ void deg_kernel(const int* __restrict__ col) {
    int e = blockIdx.x * blockDim.x + threadIdx.x;
    if (e < EE) atomicAdd(&g_deg[col[e]], 1);
}

__global__ void dinv_kernel(const int* __restrict__ batch) {
    int i = blockIdx.x * blockDim.x + threadIdx.x;
    if (i < NN) {
        g_dinv[i] = rsqrtf((float)g_deg[i]);
        atomicAdd(&g_cnt[batch[i]], 1);
    }
}

// ---------------- weight split prep: W2[k,n] -> hi/lo bf16 (same layout) ----------------
__global__ void prepw_kernel(const float* __restrict__ W2) {
    int e = blockIdx.x * blockDim.x + threadIdx.x;       // 16384
    if (e >= HH * HH) return;
    float w = W2[e];
    __nv_bfloat16 wh = __float2bfloat16_rn(w);
    float wl = w - __bfloat162float(wh);
    g_Wsp[0][e] = wh;
    g_Wsp[1][e] = __float2bfloat16_rn(wl);
}

// ---------------- fused output weight: WF = W3 @ Wl, bf = b3 @ Wl + bl ----------------
__global__ void prepWF_kernel(const float* __restrict__ W3, const float* __restrict__ Wl,
                              const float* __restrict__ b3, const float* __restrict__ bl) {
    int t = blockIdx.x * blockDim.x + threadIdx.x;       // need HH*CC = 896
    if (t < HH * CC) {
        int k = t / CC, c = t % CC;
        float s = 0.f;
        #pragma unroll 8
        for (int j = 0; j < HH; ++j) s += W3[k * HH + j] * __ldg(Wl + j * CC + c);
        g_WF[t] = s;
    }
    if (t < CC) {
        float s = __ldg(bl + t);
        #pragma unroll 8
        for (int j = 0; j < HH; ++j) s += b3[j] * __ldg(Wl + j * CC + t);
        g_bf[t] = s;
    }
}

// ---------------- multi-block scan ----------------
__global__ void scanA_kernel() {
    int i = blockIdx.x * SCHUNK + threadIdx.x;
    int v = (i < NN) ? (g_deg[i] - 1) : 0;
    #pragma unroll
    for (int off = 16; off > 0; off >>= 1) v += __shfl_xor_sync(0xffffffffu, v, off);
    __shared__ int ws[8];
    int lane = threadIdx.x & 31, wid = threadIdx.x >> 5;
    if (lane == 0) ws[wid] = v;
    __syncthreads();
    if (threadIdx.x == 0) {
        int s = 0;
        #pragma unroll
        for (int j = 0; j < 8; ++j) s += ws[j];
        g_blksum[blockIdx.x] = s;
    }
}

__global__ void scanB_kernel() {
    __shared__ int sm[512];
    int t = threadIdx.x;
    int v = (t < SBLOCKS) ? g_blksum[t] : 0;
    sm[t] = v;
    __syncthreads();
    #pragma unroll
    for (int off = 1; off < 512; off <<= 1) {
        int u = (t >= off) ? sm[t - off] : 0;
        __syncthreads();
        sm[t] += u;
        __syncthreads();
    }
    if (t < SBLOCKS) g_blkoff[t] = sm[t] - v;
    if (t == SBLOCKS - 1) g_rowptr[NN] = sm[t];
}

__global__ void scanC_kernel() {
    int i = blockIdx.x * SCHUNK + threadIdx.x;
    int v = (i < NN) ? (g_deg[i] - 1) : 0;
    int lane = threadIdx.x & 31, wid = threadIdx.x >> 5;
    int inc = v;
    #pragma unroll
    for (int off = 1; off <= 16; off <<= 1) {
        int n = __shfl_up_sync(0xffffffffu, inc, off);
        if (lane >= off) inc += n;
    }
    __shared__ int ws[8];
    if (lane == 31) ws[wid] = inc;
    __syncthreads();
    if (threadIdx.x == 0) {
        int run = 0;
        #pragma unroll
        for (int j = 0; j < 8; ++j) { int t = ws[j]; ws[j] = run; run += t; }
    }
    __syncthreads();
    int ex = inc - v + ws[wid] + g_blkoff[blockIdx.x];
    if (i < NN) { g_rowptr[i] = ex; g_cursor[i] = ex; }
}

// ---------------- CSR fill ----------------
__global__ void fill_kernel(const int* __restrict__ rowi, const int* __restrict__ coli) {
    int e = blockIdx.x * blockDim.x + threadIdx.x;
    if (e >= EE) return;
    int r = rowi[e], c = coli[e];
    int p = atomicAdd(&g_cursor[c], 1);
    g_src[p] = r;
    g_w[p]   = g_dinv[r] * g_dinv[c];
}

// ---------------- layer 1 (F_IN=1 scalar aggregation + outer product) ----------------
__global__ void layer1_kernel(const float* __restrict__ x,
                              const float* __restrict__ W1,
                              const float* __restrict__ b1) {
    int warp = (blockIdx.x * blockDim.x + threadIdx.x) >> 5;
    int lane = threadIdx.x & 31;
    if (warp >= NN) return;
    const int i = warp;
    int ps = g_rowptr[i], pe = g_rowptr[i + 1];
    float s = 0.f;
    for (int p = ps + lane; p < pe; p += 32)
        s += g_w[p] * __ldg(x + g_src[p]);
    #pragma unroll
    for (int off = 16; off > 0; off >>= 1) s += __shfl_xor_sync(0xffffffffu, s, off);
    float di = g_dinv[i];
    s += di * di * __ldg(x + i);
    float4 wv = ((const float4*)W1)[lane];
    float4 bv = ((const float4*)b1)[lane];
    float4 o;
    o.x = fmaxf(s * wv.x + bv.x, 0.f);
    o.y = fmaxf(s * wv.y + bv.y, 0.f);
    o.z = fmaxf(s * wv.z + bv.z, 0.f);
    o.w = fmaxf(s * wv.w + bv.w, 0.f);
    *(float4*)(g_hA + (size_t)i * HH + lane * 4) = o;
}

// ---------------- wmma bf16 GEMM: C[N,128] = A[N,128] @ W2[128,128] -------------------
// 3-pass error-compensated split: Ah*Wh + Al*Wh + Ah*Wl, fp32 accumulators.
// 64-row tiles, two B buffers, smem = 104.4 KB -> 2 CTAs/SM (measured optimum, R8).
#define SM_A (TROWS * APAD)                    // one A tile (bf16 elems)
#define SM_B (HH * APAD)                       // one B tile
#define GEMM_SMEM ((2 * SM_A + 2 * SM_B) * 2)  // 104448 B

__global__ __launch_bounds__(256, 2) void gemm_wmma_kernel(const float* __restrict__ A,
                                                           float* __restrict__ Cout) {
    extern __shared__ __align__(16) char smx[];
    __nv_bfloat16* Ah = (__nv_bfloat16*)smx;
    __nv_bfloat16* Al = Ah + SM_A;
    __nv_bfloat16* Bh = Al + SM_A;
    __nv_bfloat16* Bl = Bh + SM_B;
    const int tid = threadIdx.x;
    const int row0 = blockIdx.x * TROWS;

    // copy pre-split W2 (row-major [k][n]) into padded smem
    {
        const uint4* wh4 = (const uint4*)g_Wsp[0];
        const uint4* wl4 = (const uint4*)g_Wsp[1];
        #pragma unroll
        for (int i = tid; i < 2048; i += 256) {      // 128 rows x 16 uint4
            int r = i >> 4, c8 = (i & 15) * 8;
            *(uint4*)(Bh + r * APAD + c8) = wh4[i];
            *(uint4*)(Bl + r * APAD + c8) = wl4[i];
        }
    }
    // convert A tile (64x128 fp32 -> bf16 hi/lo, padded rows)
    #pragma unroll
    for (int it = 0; it < 8; ++it) {
        int idx = tid + it * 256;                    // 2048 float4s
        int r = idx >> 5;
        int c = (idx & 31) * 4;
        float4 v = make_float4(0.f, 0.f, 0.f, 0.f);
        if (row0 + r < NN) v = *(const float4*)(A + (size_t)(row0 + r) * HH + c);
        __nv_bfloat162 h01 = __floats2bfloat162_rn(v.x, v.y);
        __nv_bfloat162 h23 = __floats2bfloat162_rn(v.z, v.w);
        __nv_bfloat162 l01 = __floats2bfloat162_rn(v.x - __bfloat162float(h01.x),
                                                   v.y - __bfloat162float(h01.y));
        __nv_bfloat162 l23 = __floats2bfloat162_rn(v.z - __bfloat162float(h23.x),
                                                   v.w - __bfloat162float(h23.y));
        uint2 ph, pl;
        ph.x = *reinterpret_cast<uint32_t*>(&h01);
        ph.y = *reinterpret_cast<uint32_t*>(&h23);
        pl.x = *reinterpret_cast<uint32_t*>(&l01);
        pl.y = *reinterpret_cast<uint32_t*>(&l23);
        *(uint2*)(Ah + r * APAD + c) = ph;
        *(uint2*)(Al + r * APAD + c) = pl;
    }
    __syncthreads();

    // warp tiling: 8 warps, each 16 rows x 64 cols
    const int w = tid >> 5;
    const int wr = (w >> 1) * 16;      // warp row offset (0..48)
    const int wc = (w & 1) * 64;       // warp col offset (0/64)

    wmma::fragment<wmma::accumulator, 16, 16, 16, float> c[4];
    #pragma unroll
    for (int j = 0; j < 4; ++j) wmma::fill_fragment(c[j], 0.f);

    #pragma unroll 1
    for (int pass = 0; pass < 3; ++pass) {
        const __nv_bfloat16* At = (pass == 1) ? Al : Ah;
        const __nv_bfloat16* Bt = (pass == 2) ? Bl : Bh;
        #pragma unroll 1
        for (int kt = 0; kt < 8; ++kt) {
            wmma::fragment<wmma::matrix_a, 16, 16, 16, __nv_bfloat16, wmma::row_major> a;
            wmma::fragment<wmma::matrix_b, 16, 16, 16, __nv_bfloat16, wmma::row_major> b[4];
            wmma::load_matrix_sync(a, At + wr * APAD + kt * 16, APAD);
            #pragma unroll
            for (int j = 0; j < 4; ++j)
                wmma::load_matrix_sync(b[j], Bt + (kt * 16) * APAD + wc + j * 16, APAD);
            #pragma unroll
            for (int j = 0; j < 4; ++j)
                wmma::mma_sync(c[j], a, b[j], c[j]);
        }
    }

    if (row0 + TROWS <= NN) {
        #pragma unroll
        for (int j = 0; j < 4; ++j)
            wmma::store_matrix_sync(Cout + (size_t)(row0 + wr) * HH + wc + j * 16,
                                    c[j], HH, wmma::mem_row_major);
    } else {
        // boundary tile: stage via smem (reuse Ah/Al region as float[64][128])
        float* stage = (float*)smx;
        __syncthreads();
        #pragma unroll
        for (int j = 0; j < 4; ++j)
            wmma::store_matrix_sync(stage + wr * HH + wc + j * 16, c[j], HH, wmma::mem_row_major);
        __syncthreads();
        const int valid = NN - row0;
        for (int idx = tid; idx < valid * 32; idx += 256) {
            int r = idx >> 5, cc = (idx & 31) * 4;
            *(float4*)(Cout + (size_t)(row0 + r) * HH + cc) = *(float4*)(stage + r * HH + cc);
        }
    }
}

// ---------------- propagation (exact R13 measured-best body) --------------------------
// NO launch_bounds (learned R12/R13). One-shot grid (persistence/shfl both regressed).
template <bool RELU>
__global__ void prop_kernel(const float* __restrict__ hin,
                            float* __restrict__ hout,
                            const float* __restrict__ bias) {
    int warp = (blockIdx.x * blockDim.x + threadIdx.x) >> 5;
    int lane = threadIdx.x & 31;
    if (warp >= NN) return;
    const int i = warp;
    const float di = g_dinv[i];
    float4 self = *(const float4*)(hin + (size_t)i * HH + lane * 4);
    const float w0 = di * di;
    float4 acc;
    acc.x = w0 * self.x; acc.y = w0 * self.y; acc.z = w0 * self.z; acc.w = w0 * self.w;
    int p = g_rowptr[i];
    const int pe = g_rowptr[i + 1];
    for (; p + 3 < pe; p += 4) {
        int s0 = g_src[p], s1 = g_src[p + 1], s2 = g_src[p + 2], s3 = g_src[p + 3];
        float wa = g_w[p], wb = g_w[p + 1], wc = g_w[p + 2], wd = g_w[p + 3];
        float4 v0 = *(const float4*)(hin + (size_t)s0 * HH + lane * 4);
        float4 v1 = *(const float4*)(hin + (size_t)s1 * HH + lane * 4);
        float4 v2 = *(const float4*)(hin + (size_t)s2 * HH + lane * 4);
        float4 v3 = *(const float4*)(hin + (size_t)s3 * HH + lane * 4);
        acc = f4_fma(wa, v0, acc);
        acc = f4_fma(wb, v1, acc);
        acc = f4_fma(wc, v2, acc);
        acc = f4_fma(wd, v3, acc);
    }
    for (; p < pe; ++p) {
        int s0 = g_src[p];
        float wa = g_w[p];
        float4 v0 = *(const float4*)(hin + (size_t)s0 * HH + lane * 4);
        acc = f4_fma(wa, v0, acc);
    }
    float4 b = ((const float4*)bias)[lane];
    acc.x += b.x; acc.y += b.y; acc.z += b.z; acc.w += b.w;
    if (RELU) {
        acc.x = fmaxf(acc.x, 0.f); acc.y = fmaxf(acc.y, 0.f);
        acc.z = fmaxf(acc.z, 0.f); acc.w = fmaxf(acc.w, 0.f);
    }
    *(float4*)(hout + (size_t)i * HH + lane * 4) = acc;
}

// ---------------- mean pool over u = A·h2 (in g_hB): chunked + atomic merge -----------
__global__ void pool_kernel() {
    const int b = blockIdx.x;                 // GG*PCH blocks, 128 threads
    const int g = b / PCH, ch = b % PCH;
    int start = 0;
    #pragma unroll
    for (int j = 0; j < GG; ++j) if (j < g) start += g_cnt[j];
    const int cntg = g_cnt[g];
    const int per = (cntg + PCH - 1) / PCH;
    const int lo = start + ch * per;
    int hi = lo + per;
    const int end = start + cntg;
    if (hi > end) hi = end;
    const int col = threadIdx.x;              // 128
    float s = 0.f;
    for (int r = lo; r < hi; ++r)
        s += g_hB[(size_t)r * HH + col];
    if (hi > lo) atomicAdd(&g_pool[g * HH + col], s);
}

// ---------------- final linear: out = (pool/cnt) @ (W3@Wl) + (b3@Wl+bl) ---------------
__global__ void final_kernel(float* __restrict__ out) {
    int t = threadIdx.x;
    if (t >= GG * CC) return;
    int g = t / CC, c = t % CC;
    float dot = 0.f;
    const float* pr = g_pool + g * HH;
    #pragma unroll 8
    for (int h = 0; h < HH; ++h)
        dot += pr[h] * g_WF[h * CC + c];
    float cnt = fmaxf((float)g_cnt[g], 1.f);
    out[t] = dot / cnt + g_bf[c];
}

// ---------------- launch ----------------
extern "C" void kernel_launch(void* const* d_in, const int* in_sizes, int n_in,
                              void* d_out, int out_size) {
    const float* x    = (const float*)d_in[0];
    const int*   ei   = (const int*)d_in[1];
    const int*   batch= (const int*)d_in[2];
    const float* W1   = (const float*)d_in[3];
    const float* b1   = (const float*)d_in[4];
    const float* W2   = (const float*)d_in[5];
    const float* b2   = (const float*)d_in[6];
    const float* W3   = (const float*)d_in[7];
    const float* b3   = (const float*)d_in[8];
    const float* Wl   = (const float*)d_in[9];
    const float* bl   = (const float*)d_in[10];
    float* out = (float*)d_out;

    const int* erow = ei;
    const int* ecol = ei + EE;

    float *hA, *hB, *zb;
    cudaGetSymbolAddress((void**)&hA, g_hA);
    cudaGetSymbolAddress((void**)&hB, g_hB);
    cudaGetSymbolAddress((void**)&zb, g_zbias);

    cudaFuncSetAttribute(gemm_wmma_kernel, cudaFuncAttributeMaxDynamicSharedMemorySize, GEMM_SMEM);

    const int nblkN = (NN + 255) / 256;
    const int nblkE = (EE + 255) / 256;
    const int nwarpblk = (NN + 7) / 8;

    init_kernel<<<nblkN, 256>>>();
    deg_kernel<<<nblkE, 256>>>(ecol);
    dinv_kernel<<<nblkN, 256>>>(batch);
    prepw_kernel<<<(HH * HH + 255) / 256, 256>>>(W2);
    prepWF_kernel<<<(HH * CC + 255) / 256, 256>>>(W3, Wl, b3, bl);
    scanA_kernel<<<SBLOCKS, SCHUNK>>>();
    scanB_kernel<<<1, 512>>>();
    scanC_kernel<<<SBLOCKS, SCHUNK>>>();
    fill_kernel<<<nblkE, 256>>>(erow, ecol);

    layer1_kernel<<<nwarpblk, 256>>>(x, W1, b1);                     // -> hA (h1)
    gemm_wmma_kernel<<<GT2, 256, GEMM_SMEM>>>(hA, hB);               // h1 @ W2 -> hB
    prop_kernel<true><<<nwarpblk, 256>>>(hB, hA, b2);                // -> hA (h2)
    prop_kernel<false><<<nwarpblk, 256>>>(hA, hB, zb);               // u = A*h2 -> hB
    pool_kernel<<<GG * PCH, 128>>>();                                // pool over hB
    final_kernel<<<1, 512>>>(out);                                   // (pool/cnt)@W3@Wl + bf
}